// round 1
// baseline (speedup 1.0000x reference)
#include <cuda_runtime.h>

// Problem constants
#define BB   2
#define TT   2048
#define HIDN 2048
#define NH   16
#define NKV  4
#define HD   128
#define BT   (BB*TT)          // 4096
#define QD   (NH*HD)          // 2048
#define KVD  (NKV*HD)         // 512

// Scratch (allocation-free rule: __device__ globals)
__device__ float g_q[(size_t)BT*QD];
__device__ float g_k[(size_t)BT*KVD];
__device__ float g_v[(size_t)BT*KVD];
__device__ float g_attn[(size_t)BT*QD];

// ---------------------------------------------------------------------------
// SGEMM: C[M,N] = A[M,K] * W[K,N], all row-major, M%128==0, N%128==0, K%16==0
// 256 threads, 128x128 tile, 8x8 micro-tile, TK=16
// ---------------------------------------------------------------------------
__global__ __launch_bounds__(256) void sgemm128(const float* __restrict__ A,
                                                const float* __restrict__ W,
                                                float* __restrict__ C,
                                                int M, int N, int K) {
    __shared__ float As[16][132];
    __shared__ float Bs[16][132];

    const int tid = threadIdx.x;
    const int ty  = tid >> 4;
    const int tx  = tid & 15;
    const int m0  = blockIdx.y << 7;
    const int n0  = blockIdx.x << 7;

    float acc[8][8];
#pragma unroll
    for (int i = 0; i < 8; i++)
#pragma unroll
        for (int j = 0; j < 8; j++) acc[i][j] = 0.0f;

    for (int k0 = 0; k0 < K; k0 += 16) {
#pragma unroll
        for (int ld = 0; ld < 2; ld++) {
            int idx = tid + (ld << 8);            // 0..511
            // A tile: 128 rows x 16 cols -> store transposed
            int ra = idx >> 2;
            int ca = (idx & 3) << 2;
            float4 va = *(const float4*)(A + (size_t)(m0 + ra) * K + k0 + ca);
            As[ca + 0][ra] = va.x;
            As[ca + 1][ra] = va.y;
            As[ca + 2][ra] = va.z;
            As[ca + 3][ra] = va.w;
            // B tile: 16 rows x 128 cols
            int rb = idx >> 5;
            int cb = (idx & 31) << 2;
            *(float4*)&Bs[rb][cb] = *(const float4*)(W + (size_t)(k0 + rb) * N + n0 + cb);
        }
        __syncthreads();

#pragma unroll
        for (int kk = 0; kk < 16; kk++) {
            float a[8], b[8];
            *(float4*)&a[0] = *(float4*)&As[kk][(ty << 3)];
            *(float4*)&a[4] = *(float4*)&As[kk][(ty << 3) + 4];
            *(float4*)&b[0] = *(float4*)&Bs[kk][(tx << 3)];
            *(float4*)&b[4] = *(float4*)&Bs[kk][(tx << 3) + 4];
#pragma unroll
            for (int i = 0; i < 8; i++)
#pragma unroll
                for (int j = 0; j < 8; j++)
                    acc[i][j] += a[i] * b[j];
        }
        __syncthreads();
    }

#pragma unroll
    for (int i = 0; i < 8; i++) {
        float4* dst = (float4*)(C + (size_t)(m0 + (ty << 3) + i) * N + n0 + (tx << 3));
        dst[0] = make_float4(acc[i][0], acc[i][1], acc[i][2], acc[i][3]);
        dst[1] = make_float4(acc[i][4], acc[i][5], acc[i][6], acc[i][7]);
    }
}

// ---------------------------------------------------------------------------
// RoPE in-place: t[row, h, :64/64:] rotated with cos/sin tables (cos[p]==cos[p+64])
// ---------------------------------------------------------------------------
__global__ void rope_kernel(float* __restrict__ t, const float* __restrict__ cosT,
                            const float* __restrict__ sinT, int nheads) {
    int idx = blockIdx.x * blockDim.x + threadIdx.x;
    int total = BT * nheads * 64;
    if (idx >= total) return;
    int p   = idx & 63;
    int h   = (idx >> 6) % nheads;
    int row = idx / (nheads << 6);
    int tp  = row & (TT - 1);
    float c = cosT[tp * HD + p];
    float s = sinT[tp * HD + p];
    float* base = t + (size_t)row * nheads * HD + h * HD;
    float x1 = base[p];
    float x2 = base[p + 64];
    base[p]      = x1 * c - x2 * s;
    base[p + 64] = x2 * c + x1 * s;
}

// ---------------------------------------------------------------------------
// Causal GQA flash attention, fp32, online softmax.
// Grid: (T/64, H, B). 256 threads. Tiles: 64 q-rows x 64 k-rows, D=128.
// ---------------------------------------------------------------------------
#define QS_STRIDE 133
#define VS_STRIDE 132
#define PS_STRIDE 68
#define ATTN_SMEM ((64*QS_STRIDE + 64*QS_STRIDE + 64*VS_STRIDE + 64*PS_STRIDE) * 4)

__global__ __launch_bounds__(256) void attn_kernel() {
    extern __shared__ float sm[];
    float* Qs = sm;                       // [64][133]
    float* Ks = Qs + 64 * QS_STRIDE;      // [64][133]
    float* Vs = Ks + 64 * QS_STRIDE;      // [64][132]
    float* Ps = Vs + 64 * VS_STRIDE;      // [64][68]

    const int tid = threadIdx.x;
    const int ty  = tid >> 4;
    const int tx  = tid & 15;
    const int qb  = blockIdx.x;
    const int hy  = blockIdx.y;
    const int b   = blockIdx.z;
    const int kvh = hy >> 2;              // GQA: repeat(k,4,axis=2) -> h//4
    const int qbase = qb << 6;
    const float scale = 0.08838834764831845f;   // 1/sqrt(128)

    // Load Q tile, pre-scaled
    for (int i = tid; i < 64 * 32; i += 256) {
        int r = i >> 5;
        int c = (i & 31) << 2;
        float4 v4 = *(const float4*)&g_q[((size_t)(b * TT + qbase + r)) * QD + hy * HD + c];
        float* dq = Qs + r * QS_STRIDE + c;
        dq[0] = v4.x * scale; dq[1] = v4.y * scale;
        dq[2] = v4.z * scale; dq[3] = v4.w * scale;
    }

    float m_i[4], l_i[4], acc[4][8];
#pragma unroll
    for (int i = 0; i < 4; i++) {
        m_i[i] = -1e30f;
        l_i[i] = 0.0f;
#pragma unroll
        for (int j = 0; j < 8; j++) acc[i][j] = 0.0f;
    }

    const int r0 = ty << 2;
    const int c0 = tx << 2;

    for (int kb = 0; kb <= qb; kb++) {
        __syncthreads();   // previous tile fully consumed (also covers Q-load on iter 0)
        const int kr0 = kb << 6;
        for (int i = tid; i < 64 * 32; i += 256) {
            int r = i >> 5;
            int c = (i & 31) << 2;
            size_t g = ((size_t)(b * TT + kr0 + r)) * KVD + kvh * HD + c;
            float4 k4 = *(const float4*)&g_k[g];
            float* dk = Ks + r * QS_STRIDE + c;
            dk[0] = k4.x; dk[1] = k4.y; dk[2] = k4.z; dk[3] = k4.w;
            *(float4*)&Vs[r * VS_STRIDE + c] = *(const float4*)&g_v[g];
        }
        __syncthreads();

        // S = Q K^T (4x4 micro-tile per thread)
        float s[4][4];
#pragma unroll
        for (int i = 0; i < 4; i++)
#pragma unroll
            for (int j = 0; j < 4; j++) s[i][j] = 0.0f;

#pragma unroll 4
        for (int d = 0; d < 128; d++) {
            float a[4], kf[4];
#pragma unroll
            for (int i = 0; i < 4; i++) a[i]  = Qs[(r0 + i) * QS_STRIDE + d];
#pragma unroll
            for (int j = 0; j < 4; j++) kf[j] = Ks[(c0 + j) * QS_STRIDE + d];
#pragma unroll
            for (int i = 0; i < 4; i++)
#pragma unroll
                for (int j = 0; j < 4; j++)
                    s[i][j] += a[i] * kf[j];
        }

        if (kb == qb) {
#pragma unroll
            for (int i = 0; i < 4; i++)
#pragma unroll
                for (int j = 0; j < 4; j++)
                    if (kr0 + c0 + j > qbase + r0 + i) s[i][j] = -1e30f;
        }

        // Online softmax update (row stats reduced across the 16 tx lanes)
#pragma unroll
        for (int i = 0; i < 4; i++) {
            float tm = s[i][0];
#pragma unroll
            for (int j = 1; j < 4; j++) tm = fmaxf(tm, s[i][j]);
#pragma unroll
            for (int off = 8; off > 0; off >>= 1)
                tm = fmaxf(tm, __shfl_xor_sync(0xffffffffu, tm, off));
            float mnew = fmaxf(m_i[i], tm);
            float pj[4], rsum = 0.0f;
#pragma unroll
            for (int j = 0; j < 4; j++) {
                pj[j] = __expf(s[i][j] - mnew);
                rsum += pj[j];
            }
#pragma unroll
            for (int off = 8; off > 0; off >>= 1)
                rsum += __shfl_xor_sync(0xffffffffu, rsum, off);
            float alpha = __expf(m_i[i] - mnew);
            m_i[i] = mnew;
            l_i[i] = l_i[i] * alpha + rsum;
#pragma unroll
            for (int j = 0; j < 8; j++) acc[i][j] *= alpha;
#pragma unroll
            for (int j = 0; j < 4; j++) Ps[(r0 + i) * PS_STRIDE + c0 + j] = pj[j];
        }
        __syncthreads();

        // O += P V (4 rows x 8 d-cols per thread: cols {c0..c0+3, 64+c0..64+c0+3})
#pragma unroll 4
        for (int n = 0; n < 64; n++) {
            float p[4], vv[8];
#pragma unroll
            for (int i = 0; i < 4; i++) p[i] = Ps[(r0 + i) * PS_STRIDE + n];
#pragma unroll
            for (int j = 0; j < 4; j++) {
                vv[j]     = Vs[n * VS_STRIDE + c0 + j];
                vv[4 + j] = Vs[n * VS_STRIDE + 64 + c0 + j];
            }
#pragma unroll
            for (int i = 0; i < 4; i++)
#pragma unroll
                for (int j = 0; j < 8; j++)
                    acc[i][j] += p[i] * vv[j];
        }
    }

    // Epilogue: normalize, write to g_attn in [b, t, h*D] layout
#pragma unroll
    for (int i = 0; i < 4; i++) {
        float inv = 1.0f / l_i[i];
        size_t orow = ((size_t)(b * TT + qbase + r0 + i)) * QD + hy * HD;
#pragma unroll
        for (int j = 0; j < 4; j++) {
            g_attn[orow + c0 + j]      = acc[i][j]     * inv;
            g_attn[orow + 64 + c0 + j] = acc[i][4 + j] * inv;
        }
    }
}

// ---------------------------------------------------------------------------
// Launch
// ---------------------------------------------------------------------------
extern "C" void kernel_launch(void* const* d_in, const int* in_sizes, int n_in,
                              void* d_out, int out_size) {
    const float* x  = (const float*)d_in[0];
    const float* rc = (const float*)d_in[1];
    const float* rs = (const float*)d_in[2];
    const float* Wq = (const float*)d_in[3];
    const float* Wk = (const float*)d_in[4];
    const float* Wv = (const float*)d_in[5];
    const float* Wo = (const float*)d_in[6];
    float* out = (float*)d_out;

    float *pq, *pk, *pv, *pa;
    cudaGetSymbolAddress((void**)&pq, g_q);
    cudaGetSymbolAddress((void**)&pk, g_k);
    cudaGetSymbolAddress((void**)&pv, g_v);
    cudaGetSymbolAddress((void**)&pa, g_attn);
    cudaFuncSetAttribute(attn_kernel, cudaFuncAttributeMaxDynamicSharedMemorySize, ATTN_SMEM);

    // QKV projections
    sgemm128<<<dim3(QD / 128, BT / 128), 256>>>(x, Wq, pq, BT, QD, HIDN);
    sgemm128<<<dim3(KVD / 128, BT / 128), 256>>>(x, Wk, pk, BT, KVD, HIDN);
    sgemm128<<<dim3(KVD / 128, BT / 128), 256>>>(x, Wv, pv, BT, KVD, HIDN);

    // RoPE on q and k
    rope_kernel<<<(BT * NH * 64 + 255) / 256, 256>>>(pq, rc, rs, NH);
    rope_kernel<<<(BT * NKV * 64 + 255) / 256, 256>>>(pk, rc, rs, NKV);

    // Causal GQA flash attention
    attn_kernel<<<dim3(TT / 64, NH, BB), 256, ATTN_SMEM>>>();

    // Output projection
    sgemm128<<<dim3(HIDN / 128, BT / 128), 256>>>(pa, Wo, out, BT, HIDN, QD);
}

// round 4
// speedup vs baseline: 1.5906x; 1.5906x over previous
#include <cuda_runtime.h>
#include <cuda_bf16.h>
#include <cstdint>

// Problem constants
#define BB   2
#define TT   2048
#define HIDN 2048
#define NH   16
#define NKV  4
#define HD   128
#define BT   (BB*TT)          // 4096
#define QD   (NH*HD)          // 2048
#define KVD  (NKV*HD)         // 512

// ---------------------------------------------------------------------------
// Scratch (allocation-free rule: __device__ globals)
// ---------------------------------------------------------------------------
__device__ float g_q[(size_t)BT*QD];
__device__ float g_k[(size_t)BT*KVD];
__device__ float g_v[(size_t)BT*KVD];
__device__ float g_attn[(size_t)BT*QD];

__device__ __nv_bfloat16 g_xhi[(size_t)BT*HIDN];
__device__ __nv_bfloat16 g_xlo[(size_t)BT*HIDN];
__device__ __nv_bfloat16 g_ahi[(size_t)BT*QD];
__device__ __nv_bfloat16 g_alo[(size_t)BT*QD];
__device__ __nv_bfloat16 g_wqh[(size_t)QD*HIDN];
__device__ __nv_bfloat16 g_wql[(size_t)QD*HIDN];
__device__ __nv_bfloat16 g_wkh[(size_t)KVD*HIDN];
__device__ __nv_bfloat16 g_wkl[(size_t)KVD*HIDN];
__device__ __nv_bfloat16 g_wvh[(size_t)KVD*HIDN];
__device__ __nv_bfloat16 g_wvl[(size_t)KVD*HIDN];
__device__ __nv_bfloat16 g_woh[(size_t)HIDN*QD];
__device__ __nv_bfloat16 g_wol[(size_t)HIDN*QD];

// ---------------------------------------------------------------------------
// PTX helpers (baseline PTX only — NO tcgen05; harness targets compute_103)
// ---------------------------------------------------------------------------
__device__ __forceinline__ uint32_t s2u(const void* p) {
    return (uint32_t)__cvta_generic_to_shared(p);
}
__device__ __forceinline__ void cp16(uint32_t s, const void* g) {
    asm volatile("cp.async.cg.shared.global [%0], [%1], 16;" :: "r"(s), "l"(g));
}
__device__ __forceinline__ void ldsm4(uint32_t& r0, uint32_t& r1, uint32_t& r2,
                                      uint32_t& r3, uint32_t addr) {
    asm volatile("ldmatrix.sync.aligned.m8n8.x4.shared.b16 {%0,%1,%2,%3}, [%4];"
                 : "=r"(r0), "=r"(r1), "=r"(r2), "=r"(r3) : "r"(addr));
}
__device__ __forceinline__ void mma16816(float& d0, float& d1, float& d2, float& d3,
                                         uint32_t a0, uint32_t a1, uint32_t a2, uint32_t a3,
                                         uint32_t b0, uint32_t b1) {
    asm volatile("mma.sync.aligned.m16n8k16.row.col.f32.bf16.bf16.f32 "
                 "{%0,%1,%2,%3}, {%4,%5,%6,%7}, {%8,%9}, {%0,%1,%2,%3};"
                 : "+f"(d0), "+f"(d1), "+f"(d2), "+f"(d3)
                 : "r"(a0), "r"(a1), "r"(a2), "r"(a3), "r"(b0), "r"(b1));
}

// ---------------------------------------------------------------------------
// Split fp32 -> (hi, lo) bf16, elementwise (row-major preserved)
// ---------------------------------------------------------------------------
__global__ void split_kernel(const float* __restrict__ in,
                             __nv_bfloat16* __restrict__ hi,
                             __nv_bfloat16* __restrict__ lo, int n) {
    int i = blockIdx.x * blockDim.x + threadIdx.x;
    if (i >= n) return;
    float x = in[i];
    __nv_bfloat16 h = __float2bfloat16(x);
    float r = x - __bfloat162float(h);
    hi[i] = h;
    lo[i] = __float2bfloat16(r);
}

// ---------------------------------------------------------------------------
// Transpose + split: in [R, Ncols] fp32 -> out [Ncols, R] bf16 hi/lo
// ---------------------------------------------------------------------------
__global__ void transpose_split(const float* __restrict__ in,
                                __nv_bfloat16* __restrict__ hi,
                                __nv_bfloat16* __restrict__ lo,
                                int R, int Ncols) {
    __shared__ float t[32][33];
    int r0 = blockIdx.y * 32, c0 = blockIdx.x * 32;
    int tx = threadIdx.x, ty = threadIdx.y;
    for (int i = ty; i < 32; i += 8)
        t[i][tx] = in[(size_t)(r0 + i) * Ncols + c0 + tx];
    __syncthreads();
    for (int j = ty; j < 32; j += 8) {
        float v = t[tx][j];                       // in[r0+tx][c0+j]
        __nv_bfloat16 h = __float2bfloat16(v);
        float rem = v - __bfloat162float(h);
        size_t o = (size_t)(c0 + j) * R + r0 + tx;
        hi[o] = h;
        lo[o] = __float2bfloat16(rem);
    }
}

// ---------------------------------------------------------------------------
// bf16x3 mma.sync GEMM: C[M,N] fp32 = A[M,K] @ B[N,K]^T
// A hi/lo bf16 row-major [M,K]; B hi/lo bf16 [N,K] (i.e. W^T).
// CTA 128x128, K-chunk 64, 2-stage cp.async, 256 threads (8 warps, 32x64 each)
// ---------------------------------------------------------------------------
#define KSTRB     144                    // padded row bytes (64 bf16 -> 72)
#define MAT_BYTES (128*KSTRB)            // 18432
#define STAGE_B   (4*MAT_BYTES)          // 73728
#define GEMM_SMEM (2*STAGE_B)            // 147456

__device__ __forceinline__ void load_chunk(
    uint32_t st,
    const __nv_bfloat16* __restrict__ Ah, const __nv_bfloat16* __restrict__ Al,
    const __nv_bfloat16* __restrict__ Bh, const __nv_bfloat16* __restrict__ Bl,
    int m0, int n0, int K, int c, int tid)
{
    const size_t ka = (size_t)c * 64;
#pragma unroll
    for (int i = 0; i < 4; i++) {
        int idx = tid + (i << 8);        // 0..1023
        int r = idx >> 3;
        int u = idx & 7;
        uint32_t off = (uint32_t)r * KSTRB + ((uint32_t)u << 4);
        const size_t ga = (size_t)(m0 + r) * K + ka + ((size_t)u << 3);
        const size_t gb = (size_t)(n0 + r) * K + ka + ((size_t)u << 3);
        cp16(st + off,               Ah + ga);
        cp16(st + MAT_BYTES + off,   Al + ga);
        cp16(st + 2*MAT_BYTES + off, Bh + gb);
        cp16(st + 3*MAT_BYTES + off, Bl + gb);
    }
    asm volatile("cp.async.commit_group;" ::: "memory");
}

__global__ __launch_bounds__(256, 1)
void gemm_bf16x3(const __nv_bfloat16* __restrict__ Ah, const __nv_bfloat16* __restrict__ Al,
                 const __nv_bfloat16* __restrict__ Bh, const __nv_bfloat16* __restrict__ Bl,
                 float* __restrict__ C, int M, int N, int K)
{
    extern __shared__ __align__(128) char smem[];
    uint32_t sb = s2u(smem);
    const int tid  = threadIdx.x;
    const int lane = tid & 31;
    const int wid  = tid >> 5;
    const int warp_m = wid >> 1;          // 0..3 -> 32-row slabs
    const int warp_n = wid & 1;           // 0..1 -> 64-col slabs
    const int m0 = blockIdx.y << 7;
    const int n0 = blockIdx.x << 7;
    const int nch = K >> 6;

    // Prefetch chunks 0, 1
    load_chunk(sb,           Ah, Al, Bh, Bl, m0, n0, K, 0, tid);
    load_chunk(sb + STAGE_B, Ah, Al, Bh, Bl, m0, n0, K, 1, tid);

    // Per-thread ldmatrix base offsets (bytes)
    const uint32_t a_off = (uint32_t)(warp_m * 32 + (lane & 15)) * KSTRB
                         + ((uint32_t)(lane >> 4) << 4);
    const uint32_t b_off = (uint32_t)(warp_n * 64 + (lane & 7) + ((lane >> 4) << 3)) * KSTRB
                         + ((uint32_t)((lane >> 3) & 1) << 4);

    float acc[2][8][4];
#pragma unroll
    for (int t = 0; t < 2; t++)
#pragma unroll
        for (int n = 0; n < 8; n++)
#pragma unroll
            for (int j = 0; j < 4; j++) acc[t][n][j] = 0.0f;

    for (int c = 0; c < nch; c++) {
        const uint32_t st = sb + (uint32_t)(c & 1) * STAGE_B;
        if (c == nch - 1) asm volatile("cp.async.wait_group 0;" ::: "memory");
        else              asm volatile("cp.async.wait_group 1;" ::: "memory");
        __syncthreads();

        const uint32_t sAh = st, sAl = st + MAT_BYTES;
        const uint32_t sBh = st + 2*MAT_BYTES, sBl = st + 3*MAT_BYTES;

#pragma unroll
        for (int ks = 0; ks < 4; ks++) {
            const uint32_t ak = a_off + (uint32_t)ks * 32;
            const uint32_t bk = b_off + (uint32_t)ks * 32;
            uint32_t ah[2][4], al[2][4], bh[4][4], bl[4][4];
#pragma unroll
            for (int t = 0; t < 2; t++) {
                ldsm4(ah[t][0], ah[t][1], ah[t][2], ah[t][3], sAh + ak + t*16*KSTRB);
                ldsm4(al[t][0], al[t][1], al[t][2], al[t][3], sAl + ak + t*16*KSTRB);
            }
#pragma unroll
            for (int p = 0; p < 4; p++) {
                ldsm4(bh[p][0], bh[p][1], bh[p][2], bh[p][3], sBh + bk + p*16*KSTRB);
                ldsm4(bl[p][0], bl[p][1], bl[p][2], bl[p][3], sBl + bk + p*16*KSTRB);
            }
#pragma unroll
            for (int t = 0; t < 2; t++)
#pragma unroll
                for (int n = 0; n < 8; n++) {
                    const int p = n >> 1, q = (n & 1) << 1;
                    mma16816(acc[t][n][0], acc[t][n][1], acc[t][n][2], acc[t][n][3],
                             ah[t][0], ah[t][1], ah[t][2], ah[t][3], bh[p][q], bh[p][q+1]);
                    mma16816(acc[t][n][0], acc[t][n][1], acc[t][n][2], acc[t][n][3],
                             ah[t][0], ah[t][1], ah[t][2], ah[t][3], bl[p][q], bl[p][q+1]);
                    mma16816(acc[t][n][0], acc[t][n][1], acc[t][n][2], acc[t][n][3],
                             al[t][0], al[t][1], al[t][2], al[t][3], bh[p][q], bh[p][q+1]);
                }
        }
        __syncthreads();
        if (c + 2 < nch)
            load_chunk(st, Ah, Al, Bh, Bl, m0, n0, K, c + 2, tid);
    }

    // Epilogue: D frag -> C. Thread holds rows (lane>>2, +8), cols (lane&3)*2,+1
    const int row0 = m0 + warp_m * 32 + (lane >> 2);
    const int col0 = n0 + warp_n * 64 + ((lane & 3) << 1);
#pragma unroll
    for (int t = 0; t < 2; t++) {
#pragma unroll
        for (int n = 0; n < 8; n++) {
            float* p0 = C + (size_t)(row0 + t*16)     * N + col0 + n*8;
            float* p1 = C + (size_t)(row0 + t*16 + 8) * N + col0 + n*8;
            *(float2*)p0 = make_float2(acc[t][n][0], acc[t][n][1]);
            *(float2*)p1 = make_float2(acc[t][n][2], acc[t][n][3]);
        }
    }
}

// ---------------------------------------------------------------------------
// RoPE in-place
// ---------------------------------------------------------------------------
__global__ void rope_kernel(float* __restrict__ t, const float* __restrict__ cosT,
                            const float* __restrict__ sinT, int nheads) {
    int idx = blockIdx.x * blockDim.x + threadIdx.x;
    int total = BT * nheads * 64;
    if (idx >= total) return;
    int p   = idx & 63;
    int h   = (idx >> 6) % nheads;
    int row = idx / (nheads << 6);
    int tp  = row & (TT - 1);
    float c = cosT[tp * HD + p];
    float s = sinT[tp * HD + p];
    float* base = t + (size_t)row * nheads * HD + h * HD;
    float x1 = base[p];
    float x2 = base[p + 64];
    base[p]      = x1 * c - x2 * s;
    base[p + 64] = x2 * c + x1 * s;
}

// ---------------------------------------------------------------------------
// Causal GQA flash attention, fp32 (unchanged this round)
// ---------------------------------------------------------------------------
#define QS_STRIDE 133
#define VS_STRIDE 132
#define PS_STRIDE 68
#define ATTN_SMEM ((64*QS_STRIDE + 64*QS_STRIDE + 64*VS_STRIDE + 64*PS_STRIDE) * 4)

__global__ __launch_bounds__(256) void attn_kernel() {
    extern __shared__ float sm[];
    float* Qs = sm;
    float* Ks = Qs + 64 * QS_STRIDE;
    float* Vs = Ks + 64 * QS_STRIDE;
    float* Ps = Vs + 64 * VS_STRIDE;

    const int tid = threadIdx.x;
    const int ty  = tid >> 4;
    const int tx  = tid & 15;
    const int qb  = blockIdx.x;
    const int hy  = blockIdx.y;
    const int b   = blockIdx.z;
    const int kvh = hy >> 2;
    const int qbase = qb << 6;
    const float scale = 0.08838834764831845f;

    for (int i = tid; i < 64 * 32; i += 256) {
        int r = i >> 5;
        int c = (i & 31) << 2;
        float4 v4 = *(const float4*)&g_q[((size_t)(b * TT + qbase + r)) * QD + hy * HD + c];
        float* dq = Qs + r * QS_STRIDE + c;
        dq[0] = v4.x * scale; dq[1] = v4.y * scale;
        dq[2] = v4.z * scale; dq[3] = v4.w * scale;
    }

    float m_i[4], l_i[4], acc[4][8];
#pragma unroll
    for (int i = 0; i < 4; i++) {
        m_i[i] = -1e30f;
        l_i[i] = 0.0f;
#pragma unroll
        for (int j = 0; j < 8; j++) acc[i][j] = 0.0f;
    }

    const int r0 = ty << 2;
    const int c0 = tx << 2;

    for (int kb = 0; kb <= qb; kb++) {
        __syncthreads();
        const int kr0 = kb << 6;
        for (int i = tid; i < 64 * 32; i += 256) {
            int r = i >> 5;
            int c = (i & 31) << 2;
            size_t g = ((size_t)(b * TT + kr0 + r)) * KVD + kvh * HD + c;
            float4 k4 = *(const float4*)&g_k[g];
            float* dk = Ks + r * QS_STRIDE + c;
            dk[0] = k4.x; dk[1] = k4.y; dk[2] = k4.z; dk[3] = k4.w;
            *(float4*)&Vs[r * VS_STRIDE + c] = *(const float4*)&g_v[g];
        }
        __syncthreads();

        float s[4][4];
#pragma unroll
        for (int i = 0; i < 4; i++)
#pragma unroll
            for (int j = 0; j < 4; j++) s[i][j] = 0.0f;

#pragma unroll 4
        for (int d = 0; d < 128; d++) {
            float a[4], kf[4];
#pragma unroll
            for (int i = 0; i < 4; i++) a[i]  = Qs[(r0 + i) * QS_STRIDE + d];
#pragma unroll
            for (int j = 0; j < 4; j++) kf[j] = Ks[(c0 + j) * QS_STRIDE + d];
#pragma unroll
            for (int i = 0; i < 4; i++)
#pragma unroll
                for (int j = 0; j < 4; j++)
                    s[i][j] += a[i] * kf[j];
        }

        if (kb == qb) {
#pragma unroll
            for (int i = 0; i < 4; i++)
#pragma unroll
                for (int j = 0; j < 4; j++)
                    if (kr0 + c0 + j > qbase + r0 + i) s[i][j] = -1e30f;
        }

#pragma unroll
        for (int i = 0; i < 4; i++) {
            float tm = s[i][0];
#pragma unroll
            for (int j = 1; j < 4; j++) tm = fmaxf(tm, s[i][j]);
#pragma unroll
            for (int off = 8; off > 0; off >>= 1)
                tm = fmaxf(tm, __shfl_xor_sync(0xffffffffu, tm, off));
            float mnew = fmaxf(m_i[i], tm);
            float pj[4], rsum = 0.0f;
#pragma unroll
            for (int j = 0; j < 4; j++) {
                pj[j] = __expf(s[i][j] - mnew);
                rsum += pj[j];
            }
#pragma unroll
            for (int off = 8; off > 0; off >>= 1)
                rsum += __shfl_xor_sync(0xffffffffu, rsum, off);
            float alpha = __expf(m_i[i] - mnew);
            m_i[i] = mnew;
            l_i[i] = l_i[i] * alpha + rsum;
#pragma unroll
            for (int j = 0; j < 8; j++) acc[i][j] *= alpha;
#pragma unroll
            for (int j = 0; j < 4; j++) Ps[(r0 + i) * PS_STRIDE + c0 + j] = pj[j];
        }
        __syncthreads();

#pragma unroll 4
        for (int n = 0; n < 64; n++) {
            float p[4], vv[8];
#pragma unroll
            for (int i = 0; i < 4; i++) p[i] = Ps[(r0 + i) * PS_STRIDE + n];
#pragma unroll
            for (int j = 0; j < 4; j++) {
                vv[j]     = Vs[n * VS_STRIDE + c0 + j];
                vv[4 + j] = Vs[n * VS_STRIDE + 64 + c0 + j];
            }
#pragma unroll
            for (int i = 0; i < 4; i++)
#pragma unroll
                for (int j = 0; j < 8; j++)
                    acc[i][j] += p[i] * vv[j];
        }
    }

#pragma unroll
    for (int i = 0; i < 4; i++) {
        float inv = 1.0f / l_i[i];
        size_t orow = ((size_t)(b * TT + qbase + r0 + i)) * QD + hy * HD;
#pragma unroll
        for (int j = 0; j < 4; j++) {
            g_attn[orow + c0 + j]      = acc[i][j]     * inv;
            g_attn[orow + 64 + c0 + j] = acc[i][4 + j] * inv;
        }
    }
}

// ---------------------------------------------------------------------------
// Launch
// ---------------------------------------------------------------------------
extern "C" void kernel_launch(void* const* d_in, const int* in_sizes, int n_in,
                              void* d_out, int out_size) {
    const float* x  = (const float*)d_in[0];
    const float* rc = (const float*)d_in[1];
    const float* rs = (const float*)d_in[2];
    const float* Wq = (const float*)d_in[3];
    const float* Wk = (const float*)d_in[4];
    const float* Wv = (const float*)d_in[5];
    const float* Wo = (const float*)d_in[6];
    float* out = (float*)d_out;

    float *pq, *pk, *pv, *pa;
    __nv_bfloat16 *xhi, *xlo, *ahi, *alo;
    __nv_bfloat16 *wqh, *wql, *wkh, *wkl, *wvh, *wvl, *woh, *wol;
    cudaGetSymbolAddress((void**)&pq,  g_q);
    cudaGetSymbolAddress((void**)&pk,  g_k);
    cudaGetSymbolAddress((void**)&pv,  g_v);
    cudaGetSymbolAddress((void**)&pa,  g_attn);
    cudaGetSymbolAddress((void**)&xhi, g_xhi);
    cudaGetSymbolAddress((void**)&xlo, g_xlo);
    cudaGetSymbolAddress((void**)&ahi, g_ahi);
    cudaGetSymbolAddress((void**)&alo, g_alo);
    cudaGetSymbolAddress((void**)&wqh, g_wqh);
    cudaGetSymbolAddress((void**)&wql, g_wql);
    cudaGetSymbolAddress((void**)&wkh, g_wkh);
    cudaGetSymbolAddress((void**)&wkl, g_wkl);
    cudaGetSymbolAddress((void**)&wvh, g_wvh);
    cudaGetSymbolAddress((void**)&wvl, g_wvl);
    cudaGetSymbolAddress((void**)&woh, g_woh);
    cudaGetSymbolAddress((void**)&wol, g_wol);

    cudaFuncSetAttribute(gemm_bf16x3, cudaFuncAttributeMaxDynamicSharedMemorySize, GEMM_SMEM);
    cudaFuncSetAttribute(attn_kernel, cudaFuncAttributeMaxDynamicSharedMemorySize, ATTN_SMEM);

    // Split x, transpose+split weights into bf16 hi/lo
    split_kernel<<<(BT*HIDN + 255)/256, 256>>>(x, xhi, xlo, BT*HIDN);
    transpose_split<<<dim3(QD/32,  HIDN/32), dim3(32,8)>>>(Wq, wqh, wql, HIDN, QD);
    transpose_split<<<dim3(KVD/32, HIDN/32), dim3(32,8)>>>(Wk, wkh, wkl, HIDN, KVD);
    transpose_split<<<dim3(KVD/32, HIDN/32), dim3(32,8)>>>(Wv, wvh, wvl, HIDN, KVD);
    transpose_split<<<dim3(HIDN/32, QD/32),  dim3(32,8)>>>(Wo, woh, wol, QD, HIDN);

    // QKV projections (mma.sync bf16x3)
    gemm_bf16x3<<<dim3(QD/128,  BT/128), 256, GEMM_SMEM>>>(xhi, xlo, wqh, wql, pq, BT, QD,  HIDN);
    gemm_bf16x3<<<dim3(KVD/128, BT/128), 256, GEMM_SMEM>>>(xhi, xlo, wkh, wkl, pk, BT, KVD, HIDN);
    gemm_bf16x3<<<dim3(KVD/128, BT/128), 256, GEMM_SMEM>>>(xhi, xlo, wvh, wvl, pv, BT, KVD, HIDN);

    // RoPE
    rope_kernel<<<(BT * NH  * 64 + 255) / 256, 256>>>(pq, rc, rs, NH);
    rope_kernel<<<(BT * NKV * 64 + 255) / 256, 256>>>(pk, rc, rs, NKV);

    // Attention (fp32)
    attn_kernel<<<dim3(TT / 64, NH, BB), 256, ATTN_SMEM>>>();

    // Output projection
    split_kernel<<<(BT*QD + 255)/256, 256>>>(pa, ahi, alo, BT*QD);
    gemm_bf16x3<<<dim3(HIDN/128, BT/128), 256, GEMM_SMEM>>>(ahi, alo, woh, wol, out, BT, HIDN, QD);
}

// round 5
// speedup vs baseline: 2.7799x; 1.7477x over previous
#include <cuda_runtime.h>
#include <cuda_bf16.h>
#include <cstdint>

// Problem constants
#define BB   2
#define TT   2048
#define HIDN 2048
#define NH   16
#define NKV  4
#define HD   128
#define BT   (BB*TT)          // 4096
#define QD   (NH*HD)          // 2048
#define KVD  (NKV*HD)         // 512

// ---------------------------------------------------------------------------
// Scratch (allocation-free rule: __device__ globals)
// ---------------------------------------------------------------------------
__device__ float g_q[(size_t)BT*QD];
__device__ float g_k[(size_t)BT*KVD];
__device__ float g_v[(size_t)BT*KVD];

__device__ __nv_bfloat16 g_xhi[(size_t)BT*HIDN];
__device__ __nv_bfloat16 g_xlo[(size_t)BT*HIDN];
__device__ __nv_bfloat16 g_ahi[(size_t)BT*QD];
__device__ __nv_bfloat16 g_alo[(size_t)BT*QD];
__device__ __nv_bfloat16 g_qhi[(size_t)BT*QD];
__device__ __nv_bfloat16 g_qlo[(size_t)BT*QD];
__device__ __nv_bfloat16 g_khi[(size_t)BT*KVD];
__device__ __nv_bfloat16 g_klo[(size_t)BT*KVD];
__device__ __nv_bfloat16 g_vthi[(size_t)BT*KVD];   // [b*KVD + ch][t]
__device__ __nv_bfloat16 g_vtlo[(size_t)BT*KVD];
__device__ __nv_bfloat16 g_wqh[(size_t)QD*HIDN];
__device__ __nv_bfloat16 g_wql[(size_t)QD*HIDN];
__device__ __nv_bfloat16 g_wkh[(size_t)KVD*HIDN];
__device__ __nv_bfloat16 g_wkl[(size_t)KVD*HIDN];
__device__ __nv_bfloat16 g_wvh[(size_t)KVD*HIDN];
__device__ __nv_bfloat16 g_wvl[(size_t)KVD*HIDN];
__device__ __nv_bfloat16 g_woh[(size_t)HIDN*QD];
__device__ __nv_bfloat16 g_wol[(size_t)HIDN*QD];

// ---------------------------------------------------------------------------
// PTX helpers (baseline PTX only — harness targets compute_103, no tcgen05)
// ---------------------------------------------------------------------------
__device__ __forceinline__ uint32_t s2u(const void* p) {
    return (uint32_t)__cvta_generic_to_shared(p);
}
__device__ __forceinline__ void cp16(uint32_t s, const void* g) {
    asm volatile("cp.async.cg.shared.global [%0], [%1], 16;" :: "r"(s), "l"(g));
}
__device__ __forceinline__ void ldsm4(uint32_t* r, uint32_t addr) {
    asm volatile("ldmatrix.sync.aligned.m8n8.x4.shared.b16 {%0,%1,%2,%3}, [%4];"
                 : "=r"(r[0]), "=r"(r[1]), "=r"(r[2]), "=r"(r[3]) : "r"(addr));
}
__device__ __forceinline__ void mma16816(float* d,
                                         const uint32_t* a, uint32_t b0, uint32_t b1) {
    asm volatile("mma.sync.aligned.m16n8k16.row.col.f32.bf16.bf16.f32 "
                 "{%0,%1,%2,%3}, {%4,%5,%6,%7}, {%8,%9}, {%0,%1,%2,%3};"
                 : "+f"(d[0]), "+f"(d[1]), "+f"(d[2]), "+f"(d[3])
                 : "r"(a[0]), "r"(a[1]), "r"(a[2]), "r"(a[3]), "r"(b0), "r"(b1));
}
// split two floats into packed bf16 hi and lo registers
__device__ __forceinline__ void split2(float v0, float v1, uint32_t& hi, uint32_t& lo) {
    __nv_bfloat16 h0 = __float2bfloat16(v0), h1 = __float2bfloat16(v1);
    __nv_bfloat16 l0 = __float2bfloat16(v0 - __bfloat162float(h0));
    __nv_bfloat16 l1 = __float2bfloat16(v1 - __bfloat162float(h1));
    __nv_bfloat162 hh; hh.x = h0; hh.y = h1;
    __nv_bfloat162 ll; ll.x = l0; ll.y = l1;
    hi = *reinterpret_cast<uint32_t*>(&hh);
    lo = *reinterpret_cast<uint32_t*>(&ll);
}

// ---------------------------------------------------------------------------
// Split fp32 -> (hi, lo) bf16, elementwise (row-major preserved)
// ---------------------------------------------------------------------------
__global__ void split_kernel(const float* __restrict__ in,
                             __nv_bfloat16* __restrict__ hi,
                             __nv_bfloat16* __restrict__ lo, int n) {
    int i = blockIdx.x * blockDim.x + threadIdx.x;
    if (i >= n) return;
    float x = in[i];
    __nv_bfloat16 h = __float2bfloat16(x);
    hi[i] = h;
    lo[i] = __float2bfloat16(x - __bfloat162float(h));
}

// ---------------------------------------------------------------------------
// Transpose + split: in [R, Ncols] fp32 -> out [Ncols, R] bf16 hi/lo
// ---------------------------------------------------------------------------
__global__ void transpose_split(const float* __restrict__ in,
                                __nv_bfloat16* __restrict__ hi,
                                __nv_bfloat16* __restrict__ lo,
                                int R, int Ncols) {
    __shared__ float t[32][33];
    int r0 = blockIdx.y * 32, c0 = blockIdx.x * 32;
    int tx = threadIdx.x, ty = threadIdx.y;
    for (int i = ty; i < 32; i += 8)
        t[i][tx] = in[(size_t)(r0 + i) * Ncols + c0 + tx];
    __syncthreads();
    for (int j = ty; j < 32; j += 8) {
        float v = t[tx][j];
        __nv_bfloat16 h = __float2bfloat16(v);
        size_t o = (size_t)(c0 + j) * R + r0 + tx;
        hi[o] = h;
        lo[o] = __float2bfloat16(v - __bfloat162float(h));
    }
}

// ---------------------------------------------------------------------------
// V transpose+split: g_v [b*TT + t][KVD] -> vt [b*KVD + ch][TT]
// ---------------------------------------------------------------------------
__global__ void vtrans_split(const float* __restrict__ v,
                             __nv_bfloat16* __restrict__ hi,
                             __nv_bfloat16* __restrict__ lo) {
    __shared__ float t[32][33];
    int t0 = blockIdx.x * 32, c0 = blockIdx.y * 32, b = blockIdx.z;
    int tx = threadIdx.x, ty = threadIdx.y;
    for (int i = ty; i < 32; i += 8)
        t[i][tx] = v[((size_t)(b * TT + t0 + i)) * KVD + c0 + tx];
    __syncthreads();
    for (int j = ty; j < 32; j += 8) {
        float val = t[tx][j];                 // v[t0+tx][c0+j]
        __nv_bfloat16 h = __float2bfloat16(val);
        size_t o = ((size_t)b * KVD + c0 + j) * TT + t0 + tx;
        hi[o] = h;
        lo[o] = __float2bfloat16(val - __bfloat162float(h));
    }
}

// ---------------------------------------------------------------------------
// RoPE + split + optional scale: fp32 in, bf16 hi/lo out
// ---------------------------------------------------------------------------
__global__ void rope_split(const float* __restrict__ t, const float* __restrict__ cosT,
                           const float* __restrict__ sinT,
                           __nv_bfloat16* __restrict__ hi, __nv_bfloat16* __restrict__ lo,
                           int nheads, float scale) {
    int idx = blockIdx.x * blockDim.x + threadIdx.x;
    int total = BT * nheads * 64;
    if (idx >= total) return;
    int p   = idx & 63;
    int h   = (idx >> 6) % nheads;
    int row = idx / (nheads << 6);
    int tp  = row & (TT - 1);
    float c = cosT[tp * HD + p];
    float s = sinT[tp * HD + p];
    const float* base = t + (size_t)row * nheads * HD + h * HD;
    float x1 = base[p];
    float x2 = base[p + 64];
    float y1 = (x1 * c - x2 * s) * scale;
    float y2 = (x2 * c + x1 * s) * scale;
    size_t o = (size_t)row * nheads * HD + h * HD;
    __nv_bfloat16 h1 = __float2bfloat16(y1);
    __nv_bfloat16 h2 = __float2bfloat16(y2);
    hi[o + p]      = h1;
    hi[o + p + 64] = h2;
    lo[o + p]      = __float2bfloat16(y1 - __bfloat162float(h1));
    lo[o + p + 64] = __float2bfloat16(y2 - __bfloat162float(h2));
}

// ---------------------------------------------------------------------------
// bf16x3 mma.sync GEMM: C[M,N] fp32 = A[M,K] @ B[N,K]^T  (3-stage pipeline)
// ---------------------------------------------------------------------------
#define KSTRB     144
#define MAT_BYTES (128*KSTRB)
#define STAGE_B   (4*MAT_BYTES)          // 73728
#define GEMM_SMEM (3*STAGE_B)            // 221184

__device__ __forceinline__ void load_chunk(
    uint32_t st,
    const __nv_bfloat16* __restrict__ Ah, const __nv_bfloat16* __restrict__ Al,
    const __nv_bfloat16* __restrict__ Bh, const __nv_bfloat16* __restrict__ Bl,
    int m0, int n0, int K, int c, int tid)
{
    const size_t ka = (size_t)c * 64;
#pragma unroll
    for (int i = 0; i < 4; i++) {
        int idx = tid + (i << 8);
        int r = idx >> 3;
        int u = idx & 7;
        uint32_t off = (uint32_t)r * KSTRB + ((uint32_t)u << 4);
        const size_t ga = (size_t)(m0 + r) * K + ka + ((size_t)u << 3);
        const size_t gb = (size_t)(n0 + r) * K + ka + ((size_t)u << 3);
        cp16(st + off,               Ah + ga);
        cp16(st + MAT_BYTES + off,   Al + ga);
        cp16(st + 2*MAT_BYTES + off, Bh + gb);
        cp16(st + 3*MAT_BYTES + off, Bl + gb);
    }
    asm volatile("cp.async.commit_group;" ::: "memory");
}

__global__ __launch_bounds__(256, 1)
void gemm_bf16x3(const __nv_bfloat16* __restrict__ Ah, const __nv_bfloat16* __restrict__ Al,
                 const __nv_bfloat16* __restrict__ Bh, const __nv_bfloat16* __restrict__ Bl,
                 float* __restrict__ C, int M, int N, int K)
{
    extern __shared__ __align__(128) char smem[];
    uint32_t sb = s2u(smem);
    const int tid  = threadIdx.x;
    const int lane = tid & 31;
    const int wid  = tid >> 5;
    const int warp_m = wid >> 1;
    const int warp_n = wid & 1;
    const int m0 = blockIdx.y << 7;
    const int n0 = blockIdx.x << 7;
    const int nch = K >> 6;              // >= 3 for all our GEMMs

    load_chunk(sb,             Ah, Al, Bh, Bl, m0, n0, K, 0, tid);
    load_chunk(sb + STAGE_B,   Ah, Al, Bh, Bl, m0, n0, K, 1, tid);
    load_chunk(sb + 2*STAGE_B, Ah, Al, Bh, Bl, m0, n0, K, 2, tid);

    const uint32_t a_off = (uint32_t)(warp_m * 32 + (lane & 15)) * KSTRB
                         + ((uint32_t)(lane >> 4) << 4);
    const uint32_t b_off = (uint32_t)(warp_n * 64 + (lane & 7) + ((lane >> 4) << 3)) * KSTRB
                         + ((uint32_t)((lane >> 3) & 1) << 4);

    float acc[2][8][4];
#pragma unroll
    for (int t = 0; t < 2; t++)
#pragma unroll
        for (int n = 0; n < 8; n++)
#pragma unroll
            for (int j = 0; j < 4; j++) acc[t][n][j] = 0.0f;

    for (int c = 0; c < nch; c++) {
        const uint32_t st = sb + (uint32_t)(c % 3) * STAGE_B;
        if (c < nch - 2) asm volatile("cp.async.wait_group 2;" ::: "memory");
        else             asm volatile("cp.async.wait_group 0;" ::: "memory");
        __syncthreads();

        const uint32_t sAh = st, sAl = st + MAT_BYTES;
        const uint32_t sBh = st + 2*MAT_BYTES, sBl = st + 3*MAT_BYTES;

#pragma unroll
        for (int ks = 0; ks < 4; ks++) {
            const uint32_t ak = a_off + (uint32_t)ks * 32;
            const uint32_t bk = b_off + (uint32_t)ks * 32;
            uint32_t ah[2][4], al[2][4], bh[4][4], bl[4][4];
#pragma unroll
            for (int t = 0; t < 2; t++) {
                ldsm4(ah[t], sAh + ak + t*16*KSTRB);
                ldsm4(al[t], sAl + ak + t*16*KSTRB);
            }
#pragma unroll
            for (int p = 0; p < 4; p++) {
                ldsm4(bh[p], sBh + bk + p*16*KSTRB);
                ldsm4(bl[p], sBl + bk + p*16*KSTRB);
            }
#pragma unroll
            for (int t = 0; t < 2; t++)
#pragma unroll
                for (int n = 0; n < 8; n++) {
                    const int p = n >> 1, q = (n & 1) << 1;
                    mma16816(acc[t][n], ah[t], bh[p][q], bh[p][q+1]);
                    mma16816(acc[t][n], ah[t], bl[p][q], bl[p][q+1]);
                    mma16816(acc[t][n], al[t], bh[p][q], bh[p][q+1]);
                }
        }
        __syncthreads();
        if (c + 3 < nch)
            load_chunk(st, Ah, Al, Bh, Bl, m0, n0, K, c + 3, tid);
    }

    const int row0 = m0 + warp_m * 32 + (lane >> 2);
    const int col0 = n0 + warp_n * 64 + ((lane & 3) << 1);
#pragma unroll
    for (int t = 0; t < 2; t++) {
#pragma unroll
        for (int n = 0; n < 8; n++) {
            float* p0 = C + (size_t)(row0 + t*16)     * N + col0 + n*8;
            float* p1 = C + (size_t)(row0 + t*16 + 8) * N + col0 + n*8;
            *(float2*)p0 = make_float2(acc[t][n][0], acc[t][n][1]);
            *(float2*)p1 = make_float2(acc[t][n][2], acc[t][n][3]);
        }
    }
}

// ---------------------------------------------------------------------------
// Tensor-core causal GQA flash attention (bf16x3).
// Grid: (T/128, NH, BB), 256 threads. Warp w owns q-rows [w*16, w*16+16).
// K-tiles of 64 rows, double-buffered. Writes ahi/alo bf16 directly.
// ---------------------------------------------------------------------------
#define QSTR 272
#define KSTR 272
#define VSTR 144
#define Q_BYTES   (128*QSTR)              // 34816
#define K_BYTES   (64*KSTR)               // 17408
#define V_BYTES   (128*VSTR)              // 18432
#define KV_STAGE  (2*K_BYTES + 2*V_BYTES) // 71680
#define ATTN_SMEM (2*Q_BYTES + 2*KV_STAGE) // 212992

__device__ __forceinline__ void attn_load_kv(uint32_t base, int b, int kvh,
                                             int kt, int tid) {
    const int kr0 = kt << 6;
#pragma unroll
    for (int i = 0; i < 4; i++) {          // K: 64 rows x 16 chunks
        int idx = tid + (i << 8);
        int r = idx >> 4, u = idx & 15;
        uint32_t off = (uint32_t)r * KSTR + ((uint32_t)u << 4);
        size_t g = ((size_t)(b * TT + kr0 + r)) * KVD + kvh * HD + ((size_t)u << 3);
        cp16(base + off,           g_khi + g);
        cp16(base + K_BYTES + off, g_klo + g);
    }
#pragma unroll
    for (int i = 0; i < 4; i++) {          // Vt: 128 rows x 8 chunks
        int idx = tid + (i << 8);
        int d = idx >> 3, u = idx & 7;
        uint32_t off = (uint32_t)d * VSTR + ((uint32_t)u << 4);
        size_t g = ((size_t)b * KVD + kvh * HD + d) * TT + kr0 + ((size_t)u << 3);
        cp16(base + 2*K_BYTES + off,           g_vthi + g);
        cp16(base + 2*K_BYTES + V_BYTES + off, g_vtlo + g);
    }
    asm volatile("cp.async.commit_group;" ::: "memory");
}

__global__ __launch_bounds__(256, 1) void attn_mma() {
    extern __shared__ __align__(128) char smem[];
    uint32_t sb = s2u(smem);
    const uint32_t sQh = sb, sQl = sb + Q_BYTES;
    const uint32_t sKV = sb + 2*Q_BYTES;

    const int tid = threadIdx.x, lane = tid & 31, w = tid >> 5;
    const int qb = (gridDim.x - 1) - blockIdx.x;   // heavy tiles first
    const int hy = blockIdx.y, b = blockIdx.z;
    const int kvh = hy >> 2;
    const int qbase = qb << 7;
    const int nkt = 2 * qb + 2;

    // Stage Q (hi/lo), grouped with KV tile 0
#pragma unroll
    for (int i = 0; i < 8; i++) {
        int idx = tid + (i << 8);
        int r = idx >> 4, u = idx & 15;
        uint32_t off = (uint32_t)r * QSTR + ((uint32_t)u << 4);
        size_t g = ((size_t)(b * TT + qbase + r)) * QD + hy * HD + ((size_t)u << 3);
        cp16(sQh + off, g_qhi + g);
        cp16(sQl + off, g_qlo + g);
    }
    attn_load_kv(sKV, b, kvh, 0, tid);             // commit (Q + KV0)
    attn_load_kv(sKV + KV_STAGE, b, kvh, 1, tid);  // commit (KV1)

    const uint32_t a_off = (uint32_t)(w * 16 + (lane & 15)) * QSTR
                         + ((uint32_t)(lane >> 4) << 4);
    const uint32_t kb_off = (uint32_t)((lane & 7) + ((lane >> 4) << 3)) * KSTR
                          + ((uint32_t)((lane >> 3) & 1) << 4);
    const uint32_t vb_off = (uint32_t)((lane & 7) + ((lane >> 4) << 3)) * VSTR
                          + ((uint32_t)((lane >> 3) & 1) << 4);

    float o[16][4];
#pragma unroll
    for (int n = 0; n < 16; n++)
#pragma unroll
        for (int j = 0; j < 4; j++) o[n][j] = 0.0f;
    float m0 = -1e30f, m1 = -1e30f, l0 = 0.0f, l1 = 0.0f;

    const int qr = qbase + w * 16 + (lane >> 2);   // row for c0/c1; c2/c3 at qr+8

    for (int kt = 0; kt < nkt; kt++) {
        const uint32_t stb = sKV + (uint32_t)(kt & 1) * KV_STAGE;
        if (kt < nkt - 1) asm volatile("cp.async.wait_group 1;" ::: "memory");
        else              asm volatile("cp.async.wait_group 0;" ::: "memory");
        __syncthreads();

        // ---- S = Q K^T (bf16x3) ----
        float sc[8][4];
#pragma unroll
        for (int n = 0; n < 8; n++)
#pragma unroll
            for (int j = 0; j < 4; j++) sc[n][j] = 0.0f;

#pragma unroll
        for (int ks = 0; ks < 8; ks++) {
            uint32_t ah[4], al[4];
            ldsm4(ah, sQh + a_off + ks*32);
            ldsm4(al, sQl + a_off + ks*32);
#pragma unroll
            for (int p = 0; p < 4; p++) {
                uint32_t kh[4], kl[4];
                uint32_t ka = kb_off + (uint32_t)p * 16 * KSTR + (uint32_t)ks * 32;
                ldsm4(kh, stb + ka);
                ldsm4(kl, stb + K_BYTES + ka);
                mma16816(sc[2*p],   ah, kh[0], kh[1]);
                mma16816(sc[2*p],   ah, kl[0], kl[1]);
                mma16816(sc[2*p],   al, kh[0], kh[1]);
                mma16816(sc[2*p+1], ah, kh[2], kh[3]);
                mma16816(sc[2*p+1], ah, kl[2], kl[3]);
                mma16816(sc[2*p+1], al, kh[2], kh[3]);
            }
        }

        // ---- causal mask ----
        const int kc0 = kt << 6;
        if (kc0 + 63 > qbase + w * 16) {
#pragma unroll
            for (int j = 0; j < 8; j++) {
                int col = kc0 + j*8 + ((lane & 3) << 1);
                if (col     > qr)     sc[j][0] = -1e30f;
                if (col + 1 > qr)     sc[j][1] = -1e30f;
                if (col     > qr + 8) sc[j][2] = -1e30f;
                if (col + 1 > qr + 8) sc[j][3] = -1e30f;
            }
        }

        // ---- online softmax ----
        float tm0 = -1e30f, tm1 = -1e30f;
#pragma unroll
        for (int j = 0; j < 8; j++) {
            tm0 = fmaxf(tm0, fmaxf(sc[j][0], sc[j][1]));
            tm1 = fmaxf(tm1, fmaxf(sc[j][2], sc[j][3]));
        }
        tm0 = fmaxf(tm0, __shfl_xor_sync(0xffffffffu, tm0, 1));
        tm0 = fmaxf(tm0, __shfl_xor_sync(0xffffffffu, tm0, 2));
        tm1 = fmaxf(tm1, __shfl_xor_sync(0xffffffffu, tm1, 1));
        tm1 = fmaxf(tm1, __shfl_xor_sync(0xffffffffu, tm1, 2));
        float mn0 = fmaxf(m0, tm0), mn1 = fmaxf(m1, tm1);
        float al0 = __expf(m0 - mn0), al1 = __expf(m1 - mn1);
        m0 = mn0; m1 = mn1;
        float rs0 = 0.0f, rs1 = 0.0f;
#pragma unroll
        for (int j = 0; j < 8; j++) {
            sc[j][0] = __expf(sc[j][0] - m0);
            sc[j][1] = __expf(sc[j][1] - m0);
            sc[j][2] = __expf(sc[j][2] - m1);
            sc[j][3] = __expf(sc[j][3] - m1);
            rs0 += sc[j][0] + sc[j][1];
            rs1 += sc[j][2] + sc[j][3];
        }
        rs0 += __shfl_xor_sync(0xffffffffu, rs0, 1);
        rs0 += __shfl_xor_sync(0xffffffffu, rs0, 2);
        rs1 += __shfl_xor_sync(0xffffffffu, rs1, 1);
        rs1 += __shfl_xor_sync(0xffffffffu, rs1, 2);
        l0 = l0 * al0 + rs0;
        l1 = l1 * al1 + rs1;
#pragma unroll
        for (int n = 0; n < 16; n++) {
            o[n][0] *= al0; o[n][1] *= al0;
            o[n][2] *= al1; o[n][3] *= al1;
        }

        // ---- O += P V (bf16x3; P frags straight from S accumulator) ----
#pragma unroll
        for (int ks = 0; ks < 4; ks++) {
            uint32_t pah[4], pal[4];
            split2(sc[2*ks][0],   sc[2*ks][1],   pah[0], pal[0]);
            split2(sc[2*ks][2],   sc[2*ks][3],   pah[1], pal[1]);
            split2(sc[2*ks+1][0], sc[2*ks+1][1], pah[2], pal[2]);
            split2(sc[2*ks+1][2], sc[2*ks+1][3], pah[3], pal[3]);
#pragma unroll
            for (int p = 0; p < 8; p++) {
                uint32_t vh[4], vl[4];
                uint32_t va = vb_off + (uint32_t)p * 16 * VSTR + (uint32_t)ks * 32;
                ldsm4(vh, stb + 2*K_BYTES + va);
                ldsm4(vl, stb + 2*K_BYTES + V_BYTES + va);
                mma16816(o[2*p],   pah, vh[0], vh[1]);
                mma16816(o[2*p],   pah, vl[0], vl[1]);
                mma16816(o[2*p],   pal, vh[0], vh[1]);
                mma16816(o[2*p+1], pah, vh[2], vh[3]);
                mma16816(o[2*p+1], pah, vl[2], vl[3]);
                mma16816(o[2*p+1], pal, vh[2], vh[3]);
            }
        }
        __syncthreads();
        if (kt + 2 < nkt)
            attn_load_kv(stb, b, kvh, kt + 2, tid);
    }

    // ---- epilogue: normalize, split to bf16 hi/lo, write ahi/alo ----
    const float inv0 = 1.0f / l0, inv1 = 1.0f / l1;
    const int row0 = qbase + w * 16 + (lane >> 2);
#pragma unroll
    for (int n = 0; n < 16; n++) {
        int dcol = n * 8 + ((lane & 3) << 1);
        size_t g0 = ((size_t)(b * TT + row0))     * QD + hy * HD + dcol;
        size_t g1 = ((size_t)(b * TT + row0 + 8)) * QD + hy * HD + dcol;
        uint32_t h, l;
        split2(o[n][0] * inv0, o[n][1] * inv0, h, l);
        *reinterpret_cast<uint32_t*>(&g_ahi[g0]) = h;
        *reinterpret_cast<uint32_t*>(&g_alo[g0]) = l;
        split2(o[n][2] * inv1, o[n][3] * inv1, h, l);
        *reinterpret_cast<uint32_t*>(&g_ahi[g1]) = h;
        *reinterpret_cast<uint32_t*>(&g_alo[g1]) = l;
    }
}

// ---------------------------------------------------------------------------
// Launch
// ---------------------------------------------------------------------------
extern "C" void kernel_launch(void* const* d_in, const int* in_sizes, int n_in,
                              void* d_out, int out_size) {
    const float* x  = (const float*)d_in[0];
    const float* rc = (const float*)d_in[1];
    const float* rs = (const float*)d_in[2];
    const float* Wq = (const float*)d_in[3];
    const float* Wk = (const float*)d_in[4];
    const float* Wv = (const float*)d_in[5];
    const float* Wo = (const float*)d_in[6];
    float* out = (float*)d_out;

    float *pq, *pk, *pv;
    __nv_bfloat16 *xhi, *xlo, *ahi, *alo, *qhi, *qlo, *khi, *klo, *vthi, *vtlo;
    __nv_bfloat16 *wqh, *wql, *wkh, *wkl, *wvh, *wvl, *woh, *wol;
    cudaGetSymbolAddress((void**)&pq,   g_q);
    cudaGetSymbolAddress((void**)&pk,   g_k);
    cudaGetSymbolAddress((void**)&pv,   g_v);
    cudaGetSymbolAddress((void**)&xhi,  g_xhi);
    cudaGetSymbolAddress((void**)&xlo,  g_xlo);
    cudaGetSymbolAddress((void**)&ahi,  g_ahi);
    cudaGetSymbolAddress((void**)&alo,  g_alo);
    cudaGetSymbolAddress((void**)&qhi,  g_qhi);
    cudaGetSymbolAddress((void**)&qlo,  g_qlo);
    cudaGetSymbolAddress((void**)&khi,  g_khi);
    cudaGetSymbolAddress((void**)&klo,  g_klo);
    cudaGetSymbolAddress((void**)&vthi, g_vthi);
    cudaGetSymbolAddress((void**)&vtlo, g_vtlo);
    cudaGetSymbolAddress((void**)&wqh,  g_wqh);
    cudaGetSymbolAddress((void**)&wql,  g_wql);
    cudaGetSymbolAddress((void**)&wkh,  g_wkh);
    cudaGetSymbolAddress((void**)&wkl,  g_wkl);
    cudaGetSymbolAddress((void**)&wvh,  g_wvh);
    cudaGetSymbolAddress((void**)&wvl,  g_wvl);
    cudaGetSymbolAddress((void**)&woh,  g_woh);
    cudaGetSymbolAddress((void**)&wol,  g_wol);

    cudaFuncSetAttribute(gemm_bf16x3, cudaFuncAttributeMaxDynamicSharedMemorySize, GEMM_SMEM);
    cudaFuncSetAttribute(attn_mma,    cudaFuncAttributeMaxDynamicSharedMemorySize, ATTN_SMEM);

    // Split x, transpose+split weights
    split_kernel<<<(BT*HIDN + 255)/256, 256>>>(x, xhi, xlo, BT*HIDN);
    transpose_split<<<dim3(QD/32,  HIDN/32), dim3(32,8)>>>(Wq, wqh, wql, HIDN, QD);
    transpose_split<<<dim3(KVD/32, HIDN/32), dim3(32,8)>>>(Wk, wkh, wkl, HIDN, KVD);
    transpose_split<<<dim3(KVD/32, HIDN/32), dim3(32,8)>>>(Wv, wvh, wvl, HIDN, KVD);
    transpose_split<<<dim3(HIDN/32, QD/32),  dim3(32,8)>>>(Wo, woh, wol, QD, HIDN);

    // QKV projections
    gemm_bf16x3<<<dim3(QD/128,  BT/128), 256, GEMM_SMEM>>>(xhi, xlo, wqh, wql, pq, BT, QD,  HIDN);
    gemm_bf16x3<<<dim3(KVD/128, BT/128), 256, GEMM_SMEM>>>(xhi, xlo, wkh, wkl, pk, BT, KVD, HIDN);
    gemm_bf16x3<<<dim3(KVD/128, BT/128), 256, GEMM_SMEM>>>(xhi, xlo, wvh, wvl, pv, BT, KVD, HIDN);

    // RoPE + split (q pre-scaled by 1/sqrt(D)); V transpose + split
    rope_split<<<(BT * NH  * 64 + 255) / 256, 256>>>(pq, rc, rs, qhi, qlo, NH, 0.08838834764831845f);
    rope_split<<<(BT * NKV * 64 + 255) / 256, 256>>>(pk, rc, rs, khi, klo, NKV, 1.0f);
    vtrans_split<<<dim3(TT/32, KVD/32, BB), dim3(32,8)>>>(pv, vthi, vtlo);

    // Tensor-core causal GQA flash attention (writes ahi/alo)
    attn_mma<<<dim3(TT/128, NH, BB), 256, ATTN_SMEM>>>();

    // Output projection
    gemm_bf16x3<<<dim3(HIDN/128, BT/128), 256, GEMM_SMEM>>>(ahi, alo, woh, wol, out, BT, HIDN, QD);
}

// round 6
// speedup vs baseline: 2.9346x; 1.0556x over previous
#include <cuda_runtime.h>
#include <cuda_bf16.h>
#include <cstdint>

// Problem constants
#define BB   2
#define TT   2048
#define HIDN 2048
#define NH   16
#define NKV  4
#define HD   128
#define BT   (BB*TT)          // 4096
#define QD   (NH*HD)          // 2048
#define KVD  (NKV*HD)         // 512
#define KVN  (2*KVD)          // 1024 (fused K|V projection width)

// ---------------------------------------------------------------------------
// Scratch (allocation-free rule: __device__ globals)
// ---------------------------------------------------------------------------
__device__ float g_q[(size_t)BT*QD];
__device__ float g_kv[(size_t)BT*KVN];              // [row][ k(512) | v(512) ]

__device__ __nv_bfloat16 g_xhi[(size_t)BT*HIDN];
__device__ __nv_bfloat16 g_xlo[(size_t)BT*HIDN];
__device__ __nv_bfloat16 g_ahi[(size_t)BT*QD];
__device__ __nv_bfloat16 g_alo[(size_t)BT*QD];
__device__ __nv_bfloat16 g_qhi[(size_t)BT*QD];
__device__ __nv_bfloat16 g_qlo[(size_t)BT*QD];
__device__ __nv_bfloat16 g_khi[(size_t)BT*KVD];
__device__ __nv_bfloat16 g_klo[(size_t)BT*KVD];
__device__ __nv_bfloat16 g_vthi[(size_t)BT*KVD];    // [b*KVD + ch][t]
__device__ __nv_bfloat16 g_vtlo[(size_t)BT*KVD];
__device__ __nv_bfloat16 g_wqh[(size_t)QD*HIDN];
__device__ __nv_bfloat16 g_wql[(size_t)QD*HIDN];
__device__ __nv_bfloat16 g_wkvh[(size_t)KVN*HIDN];  // rows 0..511 = Wk^T, 512..1023 = Wv^T
__device__ __nv_bfloat16 g_wkvl[(size_t)KVN*HIDN];
__device__ __nv_bfloat16 g_woh[(size_t)HIDN*QD];
__device__ __nv_bfloat16 g_wol[(size_t)HIDN*QD];

// ---------------------------------------------------------------------------
// PTX helpers (baseline PTX only — harness targets compute_103, no tcgen05)
// ---------------------------------------------------------------------------
__device__ __forceinline__ uint32_t s2u(const void* p) {
    return (uint32_t)__cvta_generic_to_shared(p);
}
__device__ __forceinline__ void cp16(uint32_t s, const void* g) {
    asm volatile("cp.async.cg.shared.global [%0], [%1], 16;" :: "r"(s), "l"(g));
}
__device__ __forceinline__ void ldsm4(uint32_t* r, uint32_t addr) {
    asm volatile("ldmatrix.sync.aligned.m8n8.x4.shared.b16 {%0,%1,%2,%3}, [%4];"
                 : "=r"(r[0]), "=r"(r[1]), "=r"(r[2]), "=r"(r[3]) : "r"(addr));
}
__device__ __forceinline__ void mma16816(float* d,
                                         const uint32_t* a, uint32_t b0, uint32_t b1) {
    asm volatile("mma.sync.aligned.m16n8k16.row.col.f32.bf16.bf16.f32 "
                 "{%0,%1,%2,%3}, {%4,%5,%6,%7}, {%8,%9}, {%0,%1,%2,%3};"
                 : "+f"(d[0]), "+f"(d[1]), "+f"(d[2]), "+f"(d[3])
                 : "r"(a[0]), "r"(a[1]), "r"(a[2]), "r"(a[3]), "r"(b0), "r"(b1));
}
__device__ __forceinline__ void split2(float v0, float v1, uint32_t& hi, uint32_t& lo) {
    __nv_bfloat16 h0 = __float2bfloat16(v0), h1 = __float2bfloat16(v1);
    __nv_bfloat16 l0 = __float2bfloat16(v0 - __bfloat162float(h0));
    __nv_bfloat16 l1 = __float2bfloat16(v1 - __bfloat162float(h1));
    __nv_bfloat162 hh; hh.x = h0; hh.y = h1;
    __nv_bfloat162 ll; ll.x = l0; ll.y = l1;
    hi = *reinterpret_cast<uint32_t*>(&hh);
    lo = *reinterpret_cast<uint32_t*>(&ll);
}

// ---------------------------------------------------------------------------
// Split fp32 -> (hi, lo) bf16, elementwise
// ---------------------------------------------------------------------------
__global__ void split_kernel(const float* __restrict__ in,
                             __nv_bfloat16* __restrict__ hi,
                             __nv_bfloat16* __restrict__ lo, int n) {
    int i = blockIdx.x * blockDim.x + threadIdx.x;
    if (i >= n) return;
    float x = in[i];
    __nv_bfloat16 h = __float2bfloat16(x);
    hi[i] = h;
    lo[i] = __float2bfloat16(x - __bfloat162float(h));
}

// ---------------------------------------------------------------------------
// Transpose + split: in [R, Ncols] fp32 -> out [Ncols, R] bf16 hi/lo
// ---------------------------------------------------------------------------
__global__ void transpose_split(const float* __restrict__ in,
                                __nv_bfloat16* __restrict__ hi,
                                __nv_bfloat16* __restrict__ lo,
                                int R, int Ncols) {
    __shared__ float t[32][33];
    int r0 = blockIdx.y * 32, c0 = blockIdx.x * 32;
    int tx = threadIdx.x, ty = threadIdx.y;
    for (int i = ty; i < 32; i += 8)
        t[i][tx] = in[(size_t)(r0 + i) * Ncols + c0 + tx];
    __syncthreads();
    for (int j = ty; j < 32; j += 8) {
        float v = t[tx][j];
        __nv_bfloat16 h = __float2bfloat16(v);
        size_t o = (size_t)(c0 + j) * R + r0 + tx;
        hi[o] = h;
        lo[o] = __float2bfloat16(v - __bfloat162float(h));
    }
}

// ---------------------------------------------------------------------------
// V transpose+split: g_kv [b*TT + t][KVN] (v at col 512+) -> vt [b*KVD + ch][TT]
// ---------------------------------------------------------------------------
__global__ void vtrans_split(const float* __restrict__ v,
                             __nv_bfloat16* __restrict__ hi,
                             __nv_bfloat16* __restrict__ lo) {
    __shared__ float t[32][33];
    int t0 = blockIdx.x * 32, c0 = blockIdx.y * 32, b = blockIdx.z;
    int tx = threadIdx.x, ty = threadIdx.y;
    for (int i = ty; i < 32; i += 8)
        t[i][tx] = v[((size_t)(b * TT + t0 + i)) * KVN + KVD + c0 + tx];
    __syncthreads();
    for (int j = ty; j < 32; j += 8) {
        float val = t[tx][j];
        __nv_bfloat16 h = __float2bfloat16(val);
        size_t o = ((size_t)b * KVD + c0 + j) * TT + t0 + tx;
        hi[o] = h;
        lo[o] = __float2bfloat16(val - __bfloat162float(h));
    }
}

// ---------------------------------------------------------------------------
// RoPE + split + optional scale: fp32 in (row stride rstride), bf16 hi/lo out
// ---------------------------------------------------------------------------
__global__ void rope_split(const float* __restrict__ t, const float* __restrict__ cosT,
                           const float* __restrict__ sinT,
                           __nv_bfloat16* __restrict__ hi, __nv_bfloat16* __restrict__ lo,
                           int nheads, int rstride, float scale) {
    int idx = blockIdx.x * blockDim.x + threadIdx.x;
    int total = BT * nheads * 64;
    if (idx >= total) return;
    int p   = idx & 63;
    int h   = (idx >> 6) % nheads;
    int row = idx / (nheads << 6);
    int tp  = row & (TT - 1);
    float c = cosT[tp * HD + p];
    float s = sinT[tp * HD + p];
    const float* base = t + (size_t)row * rstride + h * HD;
    float x1 = base[p];
    float x2 = base[p + 64];
    float y1 = (x1 * c - x2 * s) * scale;
    float y2 = (x2 * c + x1 * s) * scale;
    size_t o = (size_t)row * nheads * HD + h * HD;
    __nv_bfloat16 h1 = __float2bfloat16(y1);
    __nv_bfloat16 h2 = __float2bfloat16(y2);
    hi[o + p]      = h1;
    hi[o + p + 64] = h2;
    lo[o + p]      = __float2bfloat16(y1 - __bfloat162float(h1));
    lo[o + p + 64] = __float2bfloat16(y2 - __bfloat162float(h2));
}

// ---------------------------------------------------------------------------
// bf16x3 mma.sync GEMM: C[M,N] fp32 = A[M,K] @ B[N,K]^T
// CTA 128x256, 8 warps (2m x 4n) of 64x64, K-chunk 64, 2-stage cp.async.
// ---------------------------------------------------------------------------
#define KSTRB     144
#define A_BYTES   (128*KSTRB)            // 18432
#define B_BYTES   (256*KSTRB)            // 36864
#define STAGE_B   (2*A_BYTES + 2*B_BYTES) // 110592
#define GEMM_SMEM (2*STAGE_B)             // 221184

__device__ __forceinline__ void load_chunk(
    uint32_t st,
    const __nv_bfloat16* __restrict__ Ah, const __nv_bfloat16* __restrict__ Al,
    const __nv_bfloat16* __restrict__ Bh, const __nv_bfloat16* __restrict__ Bl,
    int m0, int n0, int K, int c, int tid)
{
    const size_t ka = (size_t)c * 64;
#pragma unroll
    for (int i = 0; i < 4; i++) {        // A tiles: 128 rows x 8 x 16B (hi+lo)
        int idx = tid + (i << 8);
        int r = idx >> 3, u = idx & 7;
        uint32_t off = (uint32_t)r * KSTRB + ((uint32_t)u << 4);
        const size_t ga = (size_t)(m0 + r) * K + ka + ((size_t)u << 3);
        cp16(st + off,           Ah + ga);
        cp16(st + A_BYTES + off, Al + ga);
    }
#pragma unroll
    for (int i = 0; i < 8; i++) {        // B tiles: 256 rows x 8 x 16B (hi+lo)
        int idx = tid + (i << 8);
        int r = idx >> 3, u = idx & 7;
        uint32_t off = (uint32_t)r * KSTRB + ((uint32_t)u << 4);
        const size_t gb = (size_t)(n0 + r) * K + ka + ((size_t)u << 3);
        cp16(st + 2*A_BYTES + off,           Bh + gb);
        cp16(st + 2*A_BYTES + B_BYTES + off, Bl + gb);
    }
    asm volatile("cp.async.commit_group;" ::: "memory");
}

__global__ __launch_bounds__(256, 1)
void gemm_bf16x3(const __nv_bfloat16* __restrict__ Ah, const __nv_bfloat16* __restrict__ Al,
                 const __nv_bfloat16* __restrict__ Bh, const __nv_bfloat16* __restrict__ Bl,
                 float* __restrict__ C, int M, int N, int K)
{
    extern __shared__ __align__(128) char smem[];
    uint32_t sb = s2u(smem);
    const int tid  = threadIdx.x;
    const int lane = tid & 31;
    const int wid  = tid >> 5;
    const int warp_m = wid >> 2;          // 0..1 -> 64-row slabs
    const int warp_n = wid & 3;           // 0..3 -> 64-col slabs
    const int m0 = blockIdx.y << 7;
    const int n0 = blockIdx.x << 8;
    const int nch = K >> 6;

    load_chunk(sb,           Ah, Al, Bh, Bl, m0, n0, K, 0, tid);
    load_chunk(sb + STAGE_B, Ah, Al, Bh, Bl, m0, n0, K, 1, tid);

    const uint32_t a_off = (uint32_t)(warp_m * 64 + (lane & 15)) * KSTRB
                         + ((uint32_t)(lane >> 4) << 4);
    const uint32_t b_off = (uint32_t)(warp_n * 64 + (lane & 7) + ((lane >> 4) << 3)) * KSTRB
                         + ((uint32_t)((lane >> 3) & 1) << 4);

    float acc[4][8][4];
#pragma unroll
    for (int m = 0; m < 4; m++)
#pragma unroll
        for (int n = 0; n < 8; n++)
#pragma unroll
            for (int j = 0; j < 4; j++) acc[m][n][j] = 0.0f;

    for (int c = 0; c < nch; c++) {
        const uint32_t st = sb + (uint32_t)(c & 1) * STAGE_B;
        if (c == nch - 1) asm volatile("cp.async.wait_group 0;" ::: "memory");
        else              asm volatile("cp.async.wait_group 1;" ::: "memory");
        __syncthreads();

        const uint32_t sAh = st, sAl = st + A_BYTES;
        const uint32_t sBh = st + 2*A_BYTES, sBl = st + 2*A_BYTES + B_BYTES;

#pragma unroll
        for (int ks = 0; ks < 4; ks++) {
            const uint32_t ak = a_off + (uint32_t)ks * 32;
            const uint32_t bk = b_off + (uint32_t)ks * 32;
            uint32_t ah[4][4], al[4][4], bh[4][4], bl[4][4];
#pragma unroll
            for (int m = 0; m < 4; m++) {
                ldsm4(ah[m], sAh + ak + m*16*KSTRB);
                ldsm4(al[m], sAl + ak + m*16*KSTRB);
            }
#pragma unroll
            for (int p = 0; p < 4; p++) {
                ldsm4(bh[p], sBh + bk + p*16*KSTRB);
                ldsm4(bl[p], sBl + bk + p*16*KSTRB);
            }
#pragma unroll
            for (int m = 0; m < 4; m++)
#pragma unroll
                for (int n = 0; n < 8; n++) {
                    const int p = n >> 1, q = (n & 1) << 1;
                    mma16816(acc[m][n], ah[m], bh[p][q], bh[p][q+1]);
                    mma16816(acc[m][n], ah[m], bl[p][q], bl[p][q+1]);
                    mma16816(acc[m][n], al[m], bh[p][q], bh[p][q+1]);
                }
        }
        __syncthreads();
        if (c + 2 < nch)
            load_chunk(st, Ah, Al, Bh, Bl, m0, n0, K, c + 2, tid);
    }

    const int row0 = m0 + warp_m * 64 + (lane >> 2);
    const int col0 = n0 + warp_n * 64 + ((lane & 3) << 1);
#pragma unroll
    for (int m = 0; m < 4; m++) {
#pragma unroll
        for (int n = 0; n < 8; n++) {
            float* p0 = C + (size_t)(row0 + m*16)     * N + col0 + n*8;
            float* p1 = C + (size_t)(row0 + m*16 + 8) * N + col0 + n*8;
            *(float2*)p0 = make_float2(acc[m][n][0], acc[m][n][1]);
            *(float2*)p1 = make_float2(acc[m][n][2], acc[m][n][3]);
        }
    }
}

// ---------------------------------------------------------------------------
// Tensor-core causal GQA flash attention (bf16x3) — unchanged from R5.
// ---------------------------------------------------------------------------
#define QSTR 272
#define KSTR 272
#define VSTR 144
#define Q_BYTES   (128*QSTR)
#define K_BYTES   (64*KSTR)
#define V_BYTES   (128*VSTR)
#define KV_STAGE  (2*K_BYTES + 2*V_BYTES)
#define ATTN_SMEM (2*Q_BYTES + 2*KV_STAGE)

__device__ __forceinline__ void attn_load_kv(uint32_t base, int b, int kvh,
                                             int kt, int tid) {
    const int kr0 = kt << 6;
#pragma unroll
    for (int i = 0; i < 4; i++) {
        int idx = tid + (i << 8);
        int r = idx >> 4, u = idx & 15;
        uint32_t off = (uint32_t)r * KSTR + ((uint32_t)u << 4);
        size_t g = ((size_t)(b * TT + kr0 + r)) * KVD + kvh * HD + ((size_t)u << 3);
        cp16(base + off,           g_khi + g);
        cp16(base + K_BYTES + off, g_klo + g);
    }
#pragma unroll
    for (int i = 0; i < 4; i++) {
        int idx = tid + (i << 8);
        int d = idx >> 3, u = idx & 7;
        uint32_t off = (uint32_t)d * VSTR + ((uint32_t)u << 4);
        size_t g = ((size_t)b * KVD + kvh * HD + d) * TT + kr0 + ((size_t)u << 3);
        cp16(base + 2*K_BYTES + off,           g_vthi + g);
        cp16(base + 2*K_BYTES + V_BYTES + off, g_vtlo + g);
    }
    asm volatile("cp.async.commit_group;" ::: "memory");
}

__global__ __launch_bounds__(256, 1) void attn_mma() {
    extern __shared__ __align__(128) char smem[];
    uint32_t sb = s2u(smem);
    const uint32_t sQh = sb, sQl = sb + Q_BYTES;
    const uint32_t sKV = sb + 2*Q_BYTES;

    const int tid = threadIdx.x, lane = tid & 31, w = tid >> 5;
    const int qb = (gridDim.x - 1) - blockIdx.x;
    const int hy = blockIdx.y, b = blockIdx.z;
    const int kvh = hy >> 2;
    const int qbase = qb << 7;
    const int nkt = 2 * qb + 2;

#pragma unroll
    for (int i = 0; i < 8; i++) {
        int idx = tid + (i << 8);
        int r = idx >> 4, u = idx & 15;
        uint32_t off = (uint32_t)r * QSTR + ((uint32_t)u << 4);
        size_t g = ((size_t)(b * TT + qbase + r)) * QD + hy * HD + ((size_t)u << 3);
        cp16(sQh + off, g_qhi + g);
        cp16(sQl + off, g_qlo + g);
    }
    attn_load_kv(sKV, b, kvh, 0, tid);
    attn_load_kv(sKV + KV_STAGE, b, kvh, 1, tid);

    const uint32_t a_off = (uint32_t)(w * 16 + (lane & 15)) * QSTR
                         + ((uint32_t)(lane >> 4) << 4);
    const uint32_t kb_off = (uint32_t)((lane & 7) + ((lane >> 4) << 3)) * KSTR
                          + ((uint32_t)((lane >> 3) & 1) << 4);
    const uint32_t vb_off = (uint32_t)((lane & 7) + ((lane >> 4) << 3)) * VSTR
                          + ((uint32_t)((lane >> 3) & 1) << 4);

    float o[16][4];
#pragma unroll
    for (int n = 0; n < 16; n++)
#pragma unroll
        for (int j = 0; j < 4; j++) o[n][j] = 0.0f;
    float m0 = -1e30f, m1 = -1e30f, l0 = 0.0f, l1 = 0.0f;

    const int qr = qbase + w * 16 + (lane >> 2);

    for (int kt = 0; kt < nkt; kt++) {
        const uint32_t stb = sKV + (uint32_t)(kt & 1) * KV_STAGE;
        if (kt < nkt - 1) asm volatile("cp.async.wait_group 1;" ::: "memory");
        else              asm volatile("cp.async.wait_group 0;" ::: "memory");
        __syncthreads();

        float sc[8][4];
#pragma unroll
        for (int n = 0; n < 8; n++)
#pragma unroll
            for (int j = 0; j < 4; j++) sc[n][j] = 0.0f;

#pragma unroll
        for (int ks = 0; ks < 8; ks++) {
            uint32_t ah[4], al[4];
            ldsm4(ah, sQh + a_off + ks*32);
            ldsm4(al, sQl + a_off + ks*32);
#pragma unroll
            for (int p = 0; p < 4; p++) {
                uint32_t kh[4], kl[4];
                uint32_t ka = kb_off + (uint32_t)p * 16 * KSTR + (uint32_t)ks * 32;
                ldsm4(kh, stb + ka);
                ldsm4(kl, stb + K_BYTES + ka);
                mma16816(sc[2*p],   ah, kh[0], kh[1]);
                mma16816(sc[2*p],   ah, kl[0], kl[1]);
                mma16816(sc[2*p],   al, kh[0], kh[1]);
                mma16816(sc[2*p+1], ah, kh[2], kh[3]);
                mma16816(sc[2*p+1], ah, kl[2], kl[3]);
                mma16816(sc[2*p+1], al, kh[2], kh[3]);
            }
        }

        const int kc0 = kt << 6;
        if (kc0 + 63 > qbase + w * 16) {
#pragma unroll
            for (int j = 0; j < 8; j++) {
                int col = kc0 + j*8 + ((lane & 3) << 1);
                if (col     > qr)     sc[j][0] = -1e30f;
                if (col + 1 > qr)     sc[j][1] = -1e30f;
                if (col     > qr + 8) sc[j][2] = -1e30f;
                if (col + 1 > qr + 8) sc[j][3] = -1e30f;
            }
        }

        float tm0 = -1e30f, tm1 = -1e30f;
#pragma unroll
        for (int j = 0; j < 8; j++) {
            tm0 = fmaxf(tm0, fmaxf(sc[j][0], sc[j][1]));
            tm1 = fmaxf(tm1, fmaxf(sc[j][2], sc[j][3]));
        }
        tm0 = fmaxf(tm0, __shfl_xor_sync(0xffffffffu, tm0, 1));
        tm0 = fmaxf(tm0, __shfl_xor_sync(0xffffffffu, tm0, 2));
        tm1 = fmaxf(tm1, __shfl_xor_sync(0xffffffffu, tm1, 1));
        tm1 = fmaxf(tm1, __shfl_xor_sync(0xffffffffu, tm1, 2));
        float mn0 = fmaxf(m0, tm0), mn1 = fmaxf(m1, tm1);
        float al0 = __expf(m0 - mn0), al1 = __expf(m1 - mn1);
        m0 = mn0; m1 = mn1;
        float rs0 = 0.0f, rs1 = 0.0f;
#pragma unroll
        for (int j = 0; j < 8; j++) {
            sc[j][0] = __expf(sc[j][0] - m0);
            sc[j][1] = __expf(sc[j][1] - m0);
            sc[j][2] = __expf(sc[j][2] - m1);
            sc[j][3] = __expf(sc[j][3] - m1);
            rs0 += sc[j][0] + sc[j][1];
            rs1 += sc[j][2] + sc[j][3];
        }
        rs0 += __shfl_xor_sync(0xffffffffu, rs0, 1);
        rs0 += __shfl_xor_sync(0xffffffffu, rs0, 2);
        rs1 += __shfl_xor_sync(0xffffffffu, rs1, 1);
        rs1 += __shfl_xor_sync(0xffffffffu, rs1, 2);
        l0 = l0 * al0 + rs0;
        l1 = l1 * al1 + rs1;
#pragma unroll
        for (int n = 0; n < 16; n++) {
            o[n][0] *= al0; o[n][1] *= al0;
            o[n][2] *= al1; o[n][3] *= al1;
        }

#pragma unroll
        for (int ks = 0; ks < 4; ks++) {
            uint32_t pah[4], pal[4];
            split2(sc[2*ks][0],   sc[2*ks][1],   pah[0], pal[0]);
            split2(sc[2*ks][2],   sc[2*ks][3],   pah[1], pal[1]);
            split2(sc[2*ks+1][0], sc[2*ks+1][1], pah[2], pal[2]);
            split2(sc[2*ks+1][2], sc[2*ks+1][3], pah[3], pal[3]);
#pragma unroll
            for (int p = 0; p < 8; p++) {
                uint32_t vh[4], vl[4];
                uint32_t va = vb_off + (uint32_t)p * 16 * VSTR + (uint32_t)ks * 32;
                ldsm4(vh, stb + 2*K_BYTES + va);
                ldsm4(vl, stb + 2*K_BYTES + V_BYTES + va);
                mma16816(o[2*p],   pah, vh[0], vh[1]);
                mma16816(o[2*p],   pah, vl[0], vl[1]);
                mma16816(o[2*p],   pal, vh[0], vh[1]);
                mma16816(o[2*p+1], pah, vh[2], vh[3]);
                mma16816(o[2*p+1], pah, vl[2], vl[3]);
                mma16816(o[2*p+1], pal, vh[2], vh[3]);
            }
        }
        __syncthreads();
        if (kt + 2 < nkt)
            attn_load_kv(stb, b, kvh, kt + 2, tid);
    }

    const float inv0 = 1.0f / l0, inv1 = 1.0f / l1;
    const int row0 = qbase + w * 16 + (lane >> 2);
#pragma unroll
    for (int n = 0; n < 16; n++) {
        int dcol = n * 8 + ((lane & 3) << 1);
        size_t g0 = ((size_t)(b * TT + row0))     * QD + hy * HD + dcol;
        size_t g1 = ((size_t)(b * TT + row0 + 8)) * QD + hy * HD + dcol;
        uint32_t h, l;
        split2(o[n][0] * inv0, o[n][1] * inv0, h, l);
        *reinterpret_cast<uint32_t*>(&g_ahi[g0]) = h;
        *reinterpret_cast<uint32_t*>(&g_alo[g0]) = l;
        split2(o[n][2] * inv1, o[n][3] * inv1, h, l);
        *reinterpret_cast<uint32_t*>(&g_ahi[g1]) = h;
        *reinterpret_cast<uint32_t*>(&g_alo[g1]) = l;
    }
}

// ---------------------------------------------------------------------------
// Launch
// ---------------------------------------------------------------------------
extern "C" void kernel_launch(void* const* d_in, const int* in_sizes, int n_in,
                              void* d_out, int out_size) {
    const float* x  = (const float*)d_in[0];
    const float* rc = (const float*)d_in[1];
    const float* rs = (const float*)d_in[2];
    const float* Wq = (const float*)d_in[3];
    const float* Wk = (const float*)d_in[4];
    const float* Wv = (const float*)d_in[5];
    const float* Wo = (const float*)d_in[6];
    float* out = (float*)d_out;

    float *pq, *pkv;
    __nv_bfloat16 *xhi, *xlo, *ahi, *alo, *qhi, *qlo, *khi, *klo, *vthi, *vtlo;
    __nv_bfloat16 *wqh, *wql, *wkvh, *wkvl, *woh, *wol;
    cudaGetSymbolAddress((void**)&pq,   g_q);
    cudaGetSymbolAddress((void**)&pkv,  g_kv);
    cudaGetSymbolAddress((void**)&xhi,  g_xhi);
    cudaGetSymbolAddress((void**)&xlo,  g_xlo);
    cudaGetSymbolAddress((void**)&ahi,  g_ahi);
    cudaGetSymbolAddress((void**)&alo,  g_alo);
    cudaGetSymbolAddress((void**)&qhi,  g_qhi);
    cudaGetSymbolAddress((void**)&qlo,  g_qlo);
    cudaGetSymbolAddress((void**)&khi,  g_khi);
    cudaGetSymbolAddress((void**)&klo,  g_klo);
    cudaGetSymbolAddress((void**)&vthi, g_vthi);
    cudaGetSymbolAddress((void**)&vtlo, g_vtlo);
    cudaGetSymbolAddress((void**)&wqh,  g_wqh);
    cudaGetSymbolAddress((void**)&wql,  g_wql);
    cudaGetSymbolAddress((void**)&wkvh, g_wkvh);
    cudaGetSymbolAddress((void**)&wkvl, g_wkvl);
    cudaGetSymbolAddress((void**)&woh,  g_woh);
    cudaGetSymbolAddress((void**)&wol,  g_wol);

    cudaFuncSetAttribute(gemm_bf16x3, cudaFuncAttributeMaxDynamicSharedMemorySize, GEMM_SMEM);
    cudaFuncSetAttribute(attn_mma,    cudaFuncAttributeMaxDynamicSharedMemorySize, ATTN_SMEM);

    // Split x; transpose+split weights (Wk|Wv packed into one [1024][2048] buffer)
    split_kernel<<<(BT*HIDN + 255)/256, 256>>>(x, xhi, xlo, BT*HIDN);
    transpose_split<<<dim3(QD/32,  HIDN/32), dim3(32,8)>>>(Wq, wqh, wql, HIDN, QD);
    transpose_split<<<dim3(KVD/32, HIDN/32), dim3(32,8)>>>(Wk, wkvh, wkvl, HIDN, KVD);
    transpose_split<<<dim3(KVD/32, HIDN/32), dim3(32,8)>>>(Wv, wkvh + (size_t)KVD*HIDN,
                                                           wkvl + (size_t)KVD*HIDN, HIDN, KVD);
    transpose_split<<<dim3(HIDN/32, QD/32),  dim3(32,8)>>>(Wo, woh, wol, QD, HIDN);

    // Projections: Q (N=2048), fused K|V (N=1024)
    gemm_bf16x3<<<dim3(QD/256,  BT/128), 256, GEMM_SMEM>>>(xhi, xlo, wqh, wql, pq, BT, QD, HIDN);
    gemm_bf16x3<<<dim3(KVN/256, BT/128), 256, GEMM_SMEM>>>(xhi, xlo, wkvh, wkvl, pkv, BT, KVN, HIDN);

    // RoPE + split (q pre-scaled); V transpose + split (reads v half of g_kv)
    rope_split<<<(BT * NH  * 64 + 255) / 256, 256>>>(pq, rc, rs, qhi, qlo, NH, QD, 0.08838834764831845f);
    rope_split<<<(BT * NKV * 64 + 255) / 256, 256>>>(pkv, rc, rs, khi, klo, NKV, KVN, 1.0f);
    vtrans_split<<<dim3(TT/32, KVD/32, BB), dim3(32,8)>>>(pkv, vthi, vtlo);

    // Tensor-core causal GQA flash attention (writes ahi/alo)
    attn_mma<<<dim3(TT/128, NH, BB), 256, ATTN_SMEM>>>();

    // Output projection
    gemm_bf16x3<<<dim3(HIDN/256, BT/128), 256, GEMM_SMEM>>>(ahi, alo, woh, wol, out, BT, HIDN, QD);
}